// round 12
// baseline (speedup 1.0000x reference)
#include <cuda_runtime.h>
#include <math.h>

// B=32, C=32, H=64, W=64, pool 2x2 -> 32x32 pooled positions per channel.
// Block (128 thr, 4 warps) owns one (c, h2) slab.
// Lane = (i_sub, w4): 16 lanes cover a full 64-float row via float4 (2 pooled
// cells per thread), the other 16 lanes take a second batch index.
// Warp wq covers i in [8wq, 8wq+8) at 2 i's per iteration, 4 iterations.
// 9 linear batch-sums per cell; no barriers in the hot loop.
// Smem merge + nonlinear combine once per block -> one double atomicAdd.

__device__ double g_acc = 0.0;
__device__ unsigned int g_count = 0;   // self-resetting

// exp(x) on the FMA/ALU pipes, ~4e-5 rel err for |x| < 30.
__device__ __forceinline__ float fexp(float x) {
    float t  = x * 1.4426950408889634f;
    float fr = t + 12582912.0f;               // round via 1.5*2^23
    int   n  = __float_as_int(fr) - 0x4B400000;
    float f  = t - (fr - 12582912.0f);        // frac in [-0.5, 0.5]
    float p  = 0.009618130f;
    p = fmaf(p, f, 0.055504109f);
    p = fmaf(p, f, 0.240226507f);
    p = fmaf(p, f, 0.693147181f);
    p = fmaf(p, f, 1.0f);
    return __int_as_float(__float_as_int(p) + (n << 23));
}

// Update the 9 per-position sums for one pooled cell.
__device__ __forceinline__ void accum(float ma, float mb, float sa, float sb, float* A) {
    float ma2 = ma * ma, mb2 = mb * mb;
    float ra = __frcp_rn(sa), rb = __frcp_rn(sb);
    float ra2 = ra * ra,     rb2 = rb * rb;      // 1/v^2 = 256*r2 (scaled later)
    A[0] += ma;
    A[1] += fmaf(sa * sa, 0.00390625f, ma2);     // ma^2 + (sa/16)^2
    A[2] += ra2; A[3] += ma * ra2; A[4] += ma2 * ra2;
    A[5] += rb2; A[6] += mb * rb2; A[7] += mb2 * rb2;
    A[8] += __logf(sb) - __logf(sa);             // la - lb (constants cancel)
}

__global__ __launch_bounds__(128, 7) void k_main(
    const float* __restrict__ mu_a, const float* __restrict__ lv_a,
    const float* __restrict__ mu_b, const float* __restrict__ lv_b,
    float* __restrict__ out)
{
    __shared__ float s_p[8][32][9];    // [wq*2+i_sub][w2][sum]
    __shared__ bool  s_last;

    const int t     = threadIdx.x;
    const int lane  = t & 31;
    const int wq    = t >> 5;          // batch chunk 0..3 (8 i's each)
    const int i_sub = lane >> 4;       // 0/1: which i within the pair
    const int w4    = lane & 15;       // float4 column group (2 cells)
    const int b     = blockIdx.x;
    const int c     = b >> 5;
    const int h2    = b & 31;

    const int istride = 32 * 64 * 64;  // batch stride (floats)
    int ofs = (8 * wq + i_sub) * istride + (c * 64 + 2 * h2) * 64 + 4 * w4;

    float a0[9], a1[9];                // 9 sums for cell 0 (x,y) and cell 1 (z,w)
    #pragma unroll
    for (int k = 0; k < 9; k++) { a0[k] = 0.f; a1[k] = 0.f; }

    #pragma unroll
    for (int it = 0; it < 4; it++) {
        float4 A0  = *(const float4*)(mu_a + ofs);
        float4 A1  = *(const float4*)(mu_a + ofs + 64);
        float4 La0 = *(const float4*)(lv_a + ofs);
        float4 La1 = *(const float4*)(lv_a + ofs + 64);
        float4 B0  = *(const float4*)(mu_b + ofs);
        float4 B1  = *(const float4*)(mu_b + ofs + 64);
        float4 Lb0 = *(const float4*)(lv_b + ofs);
        float4 Lb1 = *(const float4*)(lv_b + ofs + 64);
        ofs += 2 * istride;

        // cell 0: components (x, y)
        {
            float ma = (A0.x + A0.y + A1.x + A1.y) * 0.25f;
            float mb = (B0.x + B0.y + B1.x + B1.y) * 0.25f;
            float sa = (__expf(La0.x) + fexp(La0.y)) + (__expf(La1.x) + fexp(La1.y));
            float sb = (__expf(Lb0.x) + fexp(Lb0.y)) + (__expf(Lb1.x) + fexp(Lb1.y));
            accum(ma, mb, sa, sb, a0);
        }
        // cell 1: components (z, w)
        {
            float ma = (A0.z + A0.w + A1.z + A1.w) * 0.25f;
            float mb = (B0.z + B0.w + B1.z + B1.w) * 0.25f;
            float sa = (__expf(La0.z) + fexp(La0.w)) + (__expf(La1.z) + fexp(La1.w));
            float sb = (__expf(Lb0.z) + fexp(Lb0.w)) + (__expf(Lb1.z) + fexp(Lb1.w));
            accum(ma, mb, sa, sb, a1);
        }
    }

    const int slot = wq * 2 + i_sub;
    #pragma unroll
    for (int k = 0; k < 9; k++) {
        s_p[slot][2 * w4][k]     = a0[k];
        s_p[slot][2 * w4 + 1][k] = a1[k];
    }
    __syncthreads();

    if (wq == 0) {
        float m[9];
        #pragma unroll
        for (int k = 0; k < 9; k++) {
            float acc = 0.f;
            #pragma unroll
            for (int s = 0; s < 8; s++) acc += s_p[s][lane][k];
            m[k] = acc;
        }

        // sum_ij diff = 32*L - 256*[0.5*SS*U0a - S1*U1a + 16*U2a]
        //                    + 256*[0.5*SS*U0b - S1*U1b + 16*U2b]
        float pa = 0.5f * m[1] * m[2] - m[0] * m[3] + 16.0f * m[4];
        float pb = 0.5f * m[1] * m[5] - m[0] * m[6] + 16.0f * m[7];
        double contrib = 32.0 * (double)m[8] + 256.0 * ((double)pb - (double)pa);

        #pragma unroll
        for (int o = 16; o; o >>= 1)
            contrib += __shfl_xor_sync(0xffffffffu, contrib, o);

        if (lane == 0) {
            atomicAdd(&g_acc, contrib);
            __threadfence();
            unsigned int prev = atomicInc(&g_count, 0xffffffffu);
            s_last = (prev == gridDim.x - 1);
        }
    }
    __syncthreads();

    if (s_last && t == 0) {
        out[0] = (float)(g_acc * (1.0 / 1024.0));   // /(B*B)
        g_acc = 0.0;                                // reset for next replay
        g_count = 0;
    }
}

extern "C" void kernel_launch(void* const* d_in, const int* in_sizes, int n_in,
                              void* d_out, int out_size) {
    const float* mu_a = (const float*)d_in[0];
    const float* lv_a = (const float*)d_in[1];
    const float* mu_b = (const float*)d_in[2];
    const float* lv_b = (const float*)d_in[3];

    k_main<<<1024, 128>>>(mu_a, lv_a, mu_b, lv_b, (float*)d_out);
}